// round 3
// baseline (speedup 1.0000x reference)
#include <cuda_runtime.h>

// Problem constants
#define B_    8
#define CIN   256
#define COUT  768
#define HWD   32
#define HW    1024
#define NH_   8
#define KS_   32
#define NG    24      // 3*NH groups
#define NPOS  25      // K*K

// Scratch (static device allocations are allowed)
__device__ float g_attn[(size_t)B_ * COUT * HW];   // 25 MB conv output
__device__ float g_inv[B_ * NG * NPOS];            // rsqrt(var+eps) per (b,g,p)
__device__ float g_mi [B_ * NG * NPOS];            // mean*inv   per (b,g,p)

// ---------------------------------------------------------------------------
// Kernel 1: attn[b,o,hw] = sum_c w[o,c]*x[b,c,hw] + bias[o]
// 128x128 block tile, 256 threads, 8x8 per thread, K-step 16
// ---------------------------------------------------------------------------
__global__ __launch_bounds__(256) void k_gemm(const float* __restrict__ x,
                                              const float* __restrict__ w,
                                              const float* __restrict__ bias) {
    __shared__ float Ws[16][128];
    __shared__ float Xs[16][128];
    const int b  = blockIdx.z;
    const int m0 = blockIdx.y * 128;
    const int n0 = blockIdx.x * 128;
    const int tid = threadIdx.x;
    const int ty = tid >> 4, tx = tid & 15;

    float acc[8][8];
#pragma unroll
    for (int i = 0; i < 8; i++)
#pragma unroll
        for (int j = 0; j < 8; j++) acc[i][j] = 0.f;

    const float* xb = x + (size_t)b * CIN * HW + n0;

    for (int k0 = 0; k0 < CIN; k0 += 16) {
        // load W tile 128x16 (transposed into Ws[k][m])
#pragma unroll
        for (int r = 0; r < 2; r++) {
            int m  = (tid >> 2) + r * 64;
            int kk = (tid & 3) * 4;
            float4 v = *(const float4*)(w + (size_t)(m0 + m) * CIN + k0 + kk);
            Ws[kk + 0][m] = v.x; Ws[kk + 1][m] = v.y;
            Ws[kk + 2][m] = v.z; Ws[kk + 3][m] = v.w;
        }
        // load X tile 16x128
#pragma unroll
        for (int r = 0; r < 2; r++) {
            int kk = (tid >> 5) + r * 8;
            int n  = (tid & 31) * 4;
            *(float4*)&Xs[kk][n] = *(const float4*)(xb + (size_t)(k0 + kk) * HW + n);
        }
        __syncthreads();
#pragma unroll
        for (int kk = 0; kk < 16; kk++) {
            float af[8], bf[8];
            *(float4*)&af[0] = *(const float4*)&Ws[kk][ty * 8];
            *(float4*)&af[4] = *(const float4*)&Ws[kk][ty * 8 + 4];
            *(float4*)&bf[0] = *(const float4*)&Xs[kk][tx * 8];
            *(float4*)&bf[4] = *(const float4*)&Xs[kk][tx * 8 + 4];
#pragma unroll
            for (int i = 0; i < 8; i++)
#pragma unroll
                for (int j = 0; j < 8; j++)
                    acc[i][j] += af[i] * bf[j];
        }
        __syncthreads();
    }

#pragma unroll
    for (int i = 0; i < 8; i++) {
        int m = m0 + ty * 8 + i;
        float bv = bias[m];
        float* o = g_attn + (size_t)(b * COUT + m) * HW + n0 + tx * 8;
        float4 r0 = make_float4(acc[i][0] + bv, acc[i][1] + bv, acc[i][2] + bv, acc[i][3] + bv);
        float4 r1 = make_float4(acc[i][4] + bv, acc[i][5] + bv, acc[i][6] + bv, acc[i][7] + bv);
        *(float4*)o       = r0;
        *(float4*)(o + 4) = r1;
    }
}

// ---------------------------------------------------------------------------
// Kernel 2: per (b, group g, shift p=(kh,kw)) mean & rstd over the clipped
// window of attn (zeros from padding count in N=32768 but add 0 to sums).
// Window rows for shift i: [max(0,i-2), min(31,i+29)]  (same for cols).
// Element (r,c) belongs to row-range i iff (i <= r+2) && (r <= i+29).
// ---------------------------------------------------------------------------
__global__ __launch_bounds__(256) void k_stats() {
    const int g = blockIdx.x;   // 0..23
    const int b = blockIdx.y;   // 0..7
    const float* base = g_attn + ((size_t)b * COUT + g * KS_) * HW;

    float acc[5][5], accq[5][5];
#pragma unroll
    for (int i = 0; i < 5; i++)
#pragma unroll
        for (int j = 0; j < 5; j++) { acc[i][j] = 0.f; accq[i][j] = 0.f; }

    for (int idx = threadIdx.x; idx < KS_ * HW; idx += 256) {
        float v  = base[idx];
        float v2 = v * v;
        int pos = idx & (HW - 1);
        int r = pos >> 5, c = pos & 31;
#pragma unroll
        for (int i = 0; i < 5; i++) {
            bool ri = (i <= r + 2) && (r <= i + 29);
#pragma unroll
            for (int j = 0; j < 5; j++) {
                bool cj = (j <= c + 2) && (c <= j + 29);
                if (ri && cj) { acc[i][j] += v; accq[i][j] += v2; }
            }
        }
    }

    __shared__ float red[50];
    if (threadIdx.x < 50) red[threadIdx.x] = 0.f;
    __syncthreads();

    const int lane = threadIdx.x & 31;
#pragma unroll
    for (int i = 0; i < 5; i++)
#pragma unroll
        for (int j = 0; j < 5; j++) {
            float s  = acc[i][j];
            float sq = accq[i][j];
#pragma unroll
            for (int o = 16; o > 0; o >>= 1) {
                s  += __shfl_down_sync(0xFFFFFFFFu, s,  o);
                sq += __shfl_down_sync(0xFFFFFFFFu, sq, o);
            }
            if (lane == 0) {
                atomicAdd(&red[i * 5 + j], s);
                atomicAdd(&red[25 + i * 5 + j], sq);
            }
        }
    __syncthreads();

    if (threadIdx.x < 25) {
        const float invN = 1.f / 32768.f;
        float s  = red[threadIdx.x];
        float sq = red[25 + threadIdx.x];
        float mean = s * invN;
        float var  = sq * invN - mean * mean;
        float inv  = rsqrtf(var + 1e-5f);
        int o = (b * NG + g) * NPOS + threadIdx.x;
        g_inv[o] = inv;
        g_mi[o]  = mean * inv;
    }
}

// ---------------------------------------------------------------------------
// Kernel 3: local attention. One block per (b, head, 16x16 spatial tile).
// smem holds the 96-channel 20x20 halo of attn for this head, plus gn params
// and folded GN stats. All normalization is folded into the FMA loops:
//   t_norm = (a*inv_p - mi_p)*gw[o] + gb[o]   (a=0 outside image).
// ---------------------------------------------------------------------------
extern __shared__ float sm3[];

__global__ __launch_bounds__(256) void k_attn(const float* __restrict__ gnw,
                                              const float* __restrict__ gnb,
                                              float* __restrict__ out) {
    const int b   = blockIdx.z;
    const int nh  = blockIdx.y;
    const int oh0 = (blockIdx.x >> 1) * 16;
    const int ow0 = (blockIdx.x & 1) * 16;
    const int tid = threadIdx.x;

    float* sA   = sm3;                 // [96][20][20]
    float* sw   = sA + 96 * 400;       // [96]
    float* sb   = sw + 96;             // [96]
    float* sinv = sb + 96;             // [3][25]  (key, q, v groups)
    float* smi  = sinv + 75;           // [3][25]

    // ---- stage attn halo ----
    const float* abase = g_attn + ((size_t)b * COUT + nh * 96) * HW;
    for (int idx = tid; idx < 96 * 400; idx += 256) {
        int ch  = idx / 400;
        int rem = idx - ch * 400;
        int lr  = rem / 20, lc = rem - lr * 20;
        int gh = oh0 - 2 + lr, gw = ow0 - 2 + lc;
        float v = 0.f;
        if ((unsigned)gh < 32u && (unsigned)gw < 32u)
            v = abase[(size_t)ch * HW + gh * 32 + gw];
        sA[idx] = v;
    }
    if (tid < 96) {
        sw[tid] = gnw[nh * 96 + tid];
        sb[tid] = gnb[nh * 96 + tid];
    }
    if (tid < 75) {
        int gg = tid / 25, p = tid - gg * 25;
        int src = (b * NG + nh * 3 + gg) * NPOS + p;
        sinv[tid] = g_inv[src];
        smi[tid]  = g_mi[src];
    }
    __syncthreads();

    const int ty = tid >> 4, tx = tid & 15;
    const int toff = ty * 20 + tx;

    // ---- Phase A: q[v] = gw_q*(sum_p(a*inv_p) - sum_p mi_p)/25 + gb_q ----
    float invq[25];
    float misum = 0.f;
#pragma unroll
    for (int p = 0; p < 25; p++) { invq[p] = sinv[25 + p]; misum += smi[25 + p]; }

    float q[32];
    {
        const float* sQ = sA + 32 * 400 + toff;
#pragma unroll
        for (int v = 0; v < 32; v++) {
            float acc = 0.f;
#pragma unroll
            for (int p = 0; p < 25; p++) {
                const int off = (p / 5) * 20 + (p % 5);
                acc += sQ[v * 400 + off] * invq[p];
            }
            float t1 = (acc - misum) * 0.04f;          // /25
            q[v] = t1 * sw[32 + v] + sb[32 + v];
        }
    }

    // ---- Phase B: sal[p] = (inv_k[p]*dot - mi_k[p]*G1 + Sqb) / sqrt(32) ----
    float invk[25], mik[25];
#pragma unroll
    for (int p = 0; p < 25; p++) { invk[p] = sinv[p]; mik[p] = smi[p]; }

    float G1 = 0.f, Sqb = 0.f;
#pragma unroll
    for (int v = 0; v < 32; v++) {
        float qg = q[v] * sw[v];
        Sqb += q[v] * sb[v];
        q[v] = qg;                    // q now holds qg
        G1 += qg;
    }

    float sal[25];
    {
        const float* sK = sA + toff;
#pragma unroll
        for (int p = 0; p < 25; p++) {
            const int off = (p / 5) * 20 + (p % 5);
            float dot = 0.f;
#pragma unroll
            for (int v = 0; v < 32; v++)
                dot += q[v] * sK[v * 400 + off];
            sal[p] = (invk[p] * dot - mik[p] * G1 + Sqb) * 0.17677669529663687f;
        }
    }

    // ---- Phase C: softmax over 25 positions ----
    float mmax = sal[0];
#pragma unroll
    for (int p = 1; p < 25; p++) mmax = fmaxf(mmax, sal[p]);
    float ssum = 0.f;
#pragma unroll
    for (int p = 0; p < 25; p++) { sal[p] = __expf(sal[p] - mmax); ssum += sal[p]; }
    const float rs = 1.f / ssum;

    // ---- Phase D: out[v] = gw_v*(sum_p wm[p]*a - C) + gb_v ----
    float wm[25];
    float C = 0.f;
#pragma unroll
    for (int p = 0; p < 25; p++) {
        float mk = sal[p] * rs;
        wm[p] = mk * sinv[50 + p];
        C += mk * smi[50 + p];
    }

    float* ob = out + ((size_t)b * 256 + nh * 32) * HW + (oh0 + ty) * 32 + (ow0 + tx);
    {
        const float* sV = sA + 64 * 400 + toff;
#pragma unroll
        for (int v = 0; v < 32; v++) {
            float acc = 0.f;
#pragma unroll
            for (int p = 0; p < 25; p++) {
                const int off = (p / 5) * 20 + (p % 5);
                acc += wm[p] * sV[v * 400 + off];
            }
            ob[(size_t)v * HW] = (acc - C) * sw[64 + v] + sb[64 + v];
        }
    }
}

// ---------------------------------------------------------------------------
extern "C" void kernel_launch(void* const* d_in, const int* in_sizes, int n_in,
                              void* d_out, int out_size) {
    const float* x      = (const float*)d_in[0];
    const float* conv_w = (const float*)d_in[1];
    const float* conv_b = (const float*)d_in[2];
    const float* gn_w   = (const float*)d_in[3];
    const float* gn_b   = (const float*)d_in[4];
    float* out = (float*)d_out;

    (void)in_sizes; (void)n_in; (void)out_size;

    const int smem3 = (96 * 400 + 96 * 2 + 75 * 2) * (int)sizeof(float); // 154,968 B
    cudaFuncSetAttribute(k_attn, cudaFuncAttributeMaxDynamicSharedMemorySize, smem3);

    dim3 g1(8, 6, B_);      // n tiles, m tiles, batch
    k_gemm<<<g1, 256>>>(x, conv_w, conv_b);

    dim3 g2(NG, B_);
    k_stats<<<g2, 256>>>();

    dim3 g3(4, NH_, B_);
    k_attn<<<g3, 256, smem3>>>(gn_w, gn_b, out);
}

// round 6
// speedup vs baseline: 1.6090x; 1.6090x over previous
#include <cuda_runtime.h>

// Problem constants
#define B_    8
#define CIN   256
#define COUT  768
#define HW    1024
#define NH_   8
#define KS_   32
#define NG    24      // 3*NH groups
#define NPOS  25      // K*K

// Scratch
__device__ float g_attn[(size_t)B_ * COUT * HW];   // 25 MB conv output (L2-resident)
__device__ float g_inv[B_ * NG * NPOS];            // rsqrt(var+eps) per (b,g,p)
__device__ float g_mi [B_ * NG * NPOS];            // mean*inv      per (b,g,p)

// ---------------- packed f32x2 helpers (Blackwell FFMA2) --------------------
__device__ __forceinline__ unsigned long long pack2dup(float x) {
    unsigned int u = __float_as_uint(x);
    unsigned long long r;
    asm("mov.b64 %0, {%1, %1};" : "=l"(r) : "r"(u));
    return r;
}
__device__ __forceinline__ float2 unpack2(unsigned long long v) {
    unsigned int lo, hi;
    asm("mov.b64 {%0, %1}, %2;" : "=r"(lo), "=r"(hi) : "l"(v));
    return make_float2(__uint_as_float(lo), __uint_as_float(hi));
}
__device__ __forceinline__ void ffma2(unsigned long long& d,
                                      unsigned long long a,
                                      unsigned long long b) {
    asm("fma.rn.f32x2 %0, %1, %2, %0;" : "+l"(d) : "l"(a), "l"(b));
}

// ---------------------------------------------------------------------------
// Kernel 1: attn[b,o,hw] = sum_c w[o,c]*x[b,c,hw] + bias[o]
// 128x128 tile, 256 threads, 8x8/thread via FFMA2 (2 fp32 FMA per issue),
// double-buffered smem.
// ---------------------------------------------------------------------------
__global__ __launch_bounds__(256, 2) void k_gemm(const float* __restrict__ x,
                                                 const float* __restrict__ w,
                                                 const float* __restrict__ bias) {
    __shared__ __align__(16) float Ws[2][16][128];
    __shared__ __align__(16) float Xs[2][16][128];
    const int b  = blockIdx.z;
    const int m0 = blockIdx.y * 128;
    const int n0 = blockIdx.x * 128;
    const int tid = threadIdx.x;
    const int ty = tid >> 4, tx = tid & 15;

    unsigned long long acc[8][4];
#pragma unroll
    for (int i = 0; i < 8; i++)
#pragma unroll
        for (int j = 0; j < 4; j++) acc[i][j] = 0ull;

    const float* xb = x + (size_t)b * CIN * HW + n0;

    const int mw  = tid >> 2;          // 0..63
    const int kk4 = (tid & 3) * 4;     // 0,4,8,12
    const int kkx = tid >> 5;          // 0..7
    const int nx  = (tid & 31) * 4;    // 0..124

    // prologue: stage 0 <- k0 = 0
    {
        float4 v0 = *(const float4*)(w + (size_t)(m0 + mw) * CIN + kk4);
        float4 v1 = *(const float4*)(w + (size_t)(m0 + mw + 64) * CIN + kk4);
        Ws[0][kk4 + 0][mw] = v0.x; Ws[0][kk4 + 1][mw] = v0.y;
        Ws[0][kk4 + 2][mw] = v0.z; Ws[0][kk4 + 3][mw] = v0.w;
        Ws[0][kk4 + 0][mw + 64] = v1.x; Ws[0][kk4 + 1][mw + 64] = v1.y;
        Ws[0][kk4 + 2][mw + 64] = v1.z; Ws[0][kk4 + 3][mw + 64] = v1.w;
        *(float4*)&Xs[0][kkx][nx]     = *(const float4*)(xb + (size_t)kkx * HW + nx);
        *(float4*)&Xs[0][kkx + 8][nx] = *(const float4*)(xb + (size_t)(kkx + 8) * HW + nx);
    }
    __syncthreads();

    int cur = 0;
    for (int k0 = 0; k0 < CIN; k0 += 16) {
        float4 pw0, pw1, px0, px1;
        const bool has = (k0 + 16 < CIN);
        if (has) {
            pw0 = *(const float4*)(w + (size_t)(m0 + mw) * CIN + k0 + 16 + kk4);
            pw1 = *(const float4*)(w + (size_t)(m0 + mw + 64) * CIN + k0 + 16 + kk4);
            px0 = *(const float4*)(xb + (size_t)(k0 + 16 + kkx) * HW + nx);
            px1 = *(const float4*)(xb + (size_t)(k0 + 16 + kkx + 8) * HW + nx);
        }
#pragma unroll
        for (int kk = 0; kk < 16; kk++) {
            float4 wa = *(const float4*)&Ws[cur][kk][ty * 8];
            float4 wb = *(const float4*)&Ws[cur][kk][ty * 8 + 4];
            ulonglong2 x0 = *(const ulonglong2*)&Xs[cur][kk][tx * 8];
            ulonglong2 x1 = *(const ulonglong2*)&Xs[cur][kk][tx * 8 + 4];
            unsigned long long a2[8];
            a2[0] = pack2dup(wa.x); a2[1] = pack2dup(wa.y);
            a2[2] = pack2dup(wa.z); a2[3] = pack2dup(wa.w);
            a2[4] = pack2dup(wb.x); a2[5] = pack2dup(wb.y);
            a2[6] = pack2dup(wb.z); a2[7] = pack2dup(wb.w);
            unsigned long long bb[4] = {x0.x, x0.y, x1.x, x1.y};
#pragma unroll
            for (int i = 0; i < 8; i++)
#pragma unroll
                for (int j = 0; j < 4; j++)
                    ffma2(acc[i][j], a2[i], bb[j]);
        }
        if (has) {
            const int nxt = cur ^ 1;
            Ws[nxt][kk4 + 0][mw] = pw0.x; Ws[nxt][kk4 + 1][mw] = pw0.y;
            Ws[nxt][kk4 + 2][mw] = pw0.z; Ws[nxt][kk4 + 3][mw] = pw0.w;
            Ws[nxt][kk4 + 0][mw + 64] = pw1.x; Ws[nxt][kk4 + 1][mw + 64] = pw1.y;
            Ws[nxt][kk4 + 2][mw + 64] = pw1.z; Ws[nxt][kk4 + 3][mw + 64] = pw1.w;
            *(float4*)&Xs[nxt][kkx][nx]     = px0;
            *(float4*)&Xs[nxt][kkx + 8][nx] = px1;
            __syncthreads();
            cur = nxt;
        }
    }

#pragma unroll
    for (int i = 0; i < 8; i++) {
        int m = m0 + ty * 8 + i;
        float bv = bias[m];
        float* o = g_attn + (size_t)(b * COUT + m) * HW + n0 + tx * 8;
        float2 r0 = unpack2(acc[i][0]);
        float2 r1 = unpack2(acc[i][1]);
        float2 r2 = unpack2(acc[i][2]);
        float2 r3 = unpack2(acc[i][3]);
        float4 s0 = make_float4(r0.x + bv, r0.y + bv, r1.x + bv, r1.y + bv);
        float4 s1 = make_float4(r2.x + bv, r2.y + bv, r3.x + bv, r3.y + bv);
        *(float4*)o       = s0;
        *(float4*)(o + 4) = s1;
    }
}

// ---------------------------------------------------------------------------
// Kernel 2: GN stats per (b, group, shift p) via separable edge algebra.
// Column windows (j): j0=[0..29] j1=[0..30] j2=[0..31] j3=[1..31] j4=[2..31]
//   colwin_j(row) from {full, c0, c1, c30, c31}.
// Row windows (i) identical over the per-row aggregates.
// ---------------------------------------------------------------------------
__global__ __launch_bounds__(256) void k_stats() {
    const int g = blockIdx.x;   // 0..23
    const int b = blockIdx.y;   // 0..7
    const float* base = g_attn + ((size_t)b * COUT + g * KS_) * HW;

    __shared__ float rowdat[32][10];
    __shared__ float edge[4][10];

    for (int i = threadIdx.x; i < 320; i += 256) ((float*)rowdat)[i] = 0.f;
    __syncthreads();

    const int r   = threadIdx.x & 31;
    const int ch0 = threadIdx.x >> 5;

    float sf = 0, qf = 0, s0 = 0, q0 = 0, s1 = 0, q1 = 0,
          s30 = 0, q30 = 0, s31 = 0, q31 = 0;
#pragma unroll
    for (int it = 0; it < 4; it++) {
        const int ch = ch0 + it * 8;
        const float4* row = (const float4*)(base + (size_t)ch * HW + r * 32);
#pragma unroll
        for (int jj = 0; jj < 8; jj++) {
            float4 v = row[jj];
            sf += v.x + v.y + v.z + v.w;
            qf += v.x * v.x + v.y * v.y + v.z * v.z + v.w * v.w;
            if (jj == 0) { s0 += v.x; q0 += v.x * v.x; s1 += v.y; q1 += v.y * v.y; }
            if (jj == 7) { s30 += v.z; q30 += v.z * v.z; s31 += v.w; q31 += v.w * v.w; }
        }
    }
    atomicAdd(&rowdat[r][0], sf);  atomicAdd(&rowdat[r][1], qf);
    atomicAdd(&rowdat[r][2], s0);  atomicAdd(&rowdat[r][3], q0);
    atomicAdd(&rowdat[r][4], s1);  atomicAdd(&rowdat[r][5], q1);
    atomicAdd(&rowdat[r][6], s30); atomicAdd(&rowdat[r][7], q30);
    atomicAdd(&rowdat[r][8], s31); atomicAdd(&rowdat[r][9], q31);
    __syncthreads();

    if (threadIdx.x < 32) {
        const int l = threadIdx.x;   // row index
        float F  = rowdat[l][0], QF = rowdat[l][1];
        float E0 = rowdat[l][2], Q0 = rowdat[l][3];
        float E1 = rowdat[l][4], Q1 = rowdat[l][5];
        float E30 = rowdat[l][6], Q30 = rowdat[l][7];
        float E31 = rowdat[l][8], Q31 = rowdat[l][9];

        float rs[5], rq[5];
        rs[0] = F - E30 - E31; rq[0] = QF - Q30 - Q31;
        rs[1] = F - E31;       rq[1] = QF - Q31;
        rs[2] = F;             rq[2] = QF;
        rs[3] = F - E0;        rq[3] = QF - Q0;
        rs[4] = F - E0 - E1;   rq[4] = QF - Q0 - Q1;

        float ts[5], tq[5];
#pragma unroll
        for (int j = 0; j < 5; j++) { ts[j] = rs[j]; tq[j] = rq[j]; }
#pragma unroll
        for (int o = 16; o > 0; o >>= 1)
#pragma unroll
            for (int j = 0; j < 5; j++) {
                ts[j] += __shfl_xor_sync(0xFFFFFFFFu, ts[j], o);
                tq[j] += __shfl_xor_sync(0xFFFFFFFFu, tq[j], o);
            }

        int ei = (l == 0) ? 0 : (l == 1) ? 1 : (l == 30) ? 2 : (l == 31) ? 3 : -1;
        if (ei >= 0)
#pragma unroll
            for (int j = 0; j < 5; j++) { edge[ei][j] = rs[j]; edge[ei][5 + j] = rq[j]; }
        __syncwarp();

        if (l < 25) {
            const int i = l / 5, j = l % 5;
            float S = ts[j], Q = tq[j];
            if (i == 0)      { S -= edge[2][j] + edge[3][j]; Q -= edge[2][5+j] + edge[3][5+j]; }
            else if (i == 1) { S -= edge[3][j];              Q -= edge[3][5+j]; }
            else if (i == 3) { S -= edge[0][j];              Q -= edge[0][5+j]; }
            else if (i == 4) { S -= edge[0][j] + edge[1][j]; Q -= edge[0][5+j] + edge[1][5+j]; }
            const float invN = 1.f / 32768.f;
            float mean = S * invN;
            float var  = Q * invN - mean * mean;
            float inv  = rsqrtf(var + 1e-5f);
            int o = (b * NG + g) * NPOS + l;
            g_inv[o] = inv;
            g_mi[o]  = mean * inv;
        }
    }
}

// ---------------------------------------------------------------------------
// Kernel 3: local attention, 32x8 spatial tile, chunked smem (one 32-channel
// group at a time -> 56.7KB -> 2 blocks/SM, single wave). Warp = one output
// row, lane = column -> stride-1 LDS, conflict-free.
// ---------------------------------------------------------------------------
#define CHUNK_F (32 * 12 * 36)   // 13824 floats

extern __shared__ float sm3[];

__global__ __launch_bounds__(256, 2) void k_attn(const float* __restrict__ gnw,
                                                 const float* __restrict__ gnb,
                                                 float* __restrict__ out) {
    const int b   = blockIdx.z;
    const int nh  = blockIdx.y;
    const int oh0 = blockIdx.x * 8;
    const int tid  = threadIdx.x;
    const int warp = tid >> 5;
    const int lane = tid & 31;

    float* sC   = sm3;               // [32][12][36]
    float* sw   = sC + CHUNK_F;      // [96]
    float* sb   = sw + 96;           // [96]
    float* sinv = sb + 96;           // [3][25]
    float* smi  = sinv + 75;         // [3][25]

    if (tid < 96) { sw[tid] = gnw[nh * 96 + tid]; sb[tid] = gnb[nh * 96 + tid]; }
    if (tid < 75) {
        int gg = tid / 25, p = tid - gg * 25;
        int src = (b * NG + nh * 3 + gg) * NPOS + p;
        sinv[tid] = g_inv[src];
        smi[tid]  = g_mi[src];
    }

    const float* abase = g_attn + ((size_t)b * COUT + nh * 96) * HW;

    // stage 32-channel chunk starting at channel cb (within this head's 96)
    auto stage = [&](int cb) {
        for (int idx = tid; idx < CHUNK_F; idx += 256) {
            int ch  = idx / 432;
            int rem = idx - ch * 432;
            int lr  = rem / 36;
            int lc  = rem - lr * 36;
            int gh = oh0 - 2 + lr;
            int gw = lc - 2;
            float v = 0.f;
            if ((unsigned)gh < 32u && (unsigned)gw < 32u)
                v = abase[(size_t)(cb + ch) * HW + gh * 32 + gw];
            sC[idx] = v;
        }
    };

    const int b0 = warp * 36 + lane;

    // ---- Phase A: Q chunk ----
    stage(32);
    __syncthreads();

    float invq[25];
    float misum = 0.f;
#pragma unroll
    for (int p = 0; p < 25; p++) { invq[p] = sinv[25 + p]; misum += smi[25 + p]; }

    float q[32];
#pragma unroll
    for (int v = 0; v < 32; v++) {
        const float* pv = sC + v * 432 + b0;
        float acc = 0.f;
#pragma unroll
        for (int i = 0; i < 5; i++)
#pragma unroll
            for (int j = 0; j < 5; j++)
                acc += pv[i * 36 + j] * invq[i * 5 + j];
        q[v] = (acc - misum) * 0.04f * sw[32 + v] + sb[32 + v];
    }

    // ---- Phase B: K chunk ----
    __syncthreads();
    stage(0);
    __syncthreads();

    float G1 = 0.f, Sqb = 0.f;
#pragma unroll
    for (int v = 0; v < 32; v++) {
        float qg = q[v] * sw[v];
        Sqb += q[v] * sb[v];
        q[v] = qg;
        G1 += qg;
    }

    float sal[25];
#pragma unroll
    for (int i = 0; i < 5; i++)
#pragma unroll
        for (int j = 0; j < 5; j++) {
            const float* pk = sC + b0 + i * 36 + j;
            float dot = 0.f;
#pragma unroll
            for (int v = 0; v < 32; v++)
                dot += q[v] * pk[v * 432];
            const int p = i * 5 + j;
            sal[p] = (sinv[p] * dot - smi[p] * G1 + Sqb) * 0.17677669529663687f;
        }

    // ---- softmax over 25 positions ----
    float mmax = sal[0];
#pragma unroll
    for (int p = 1; p < 25; p++) mmax = fmaxf(mmax, sal[p]);
    float ssum = 0.f;
#pragma unroll
    for (int p = 0; p < 25; p++) { sal[p] = __expf(sal[p] - mmax); ssum += sal[p]; }
    const float rsum = 1.f / ssum;

    float wm[25];
    float C = 0.f;
#pragma unroll
    for (int p = 0; p < 25; p++) {
        float mk = sal[p] * rsum;
        wm[p] = mk * sinv[50 + p];
        C += mk * smi[50 + p];
    }

    // ---- Phase D: V chunk ----
    __syncthreads();
    stage(64);
    __syncthreads();

    float* ob = out + ((size_t)(b * 256 + nh * 32)) * HW + (oh0 + warp) * 32 + lane;
#pragma unroll 4
    for (int v = 0; v < 32; v++) {
        const float* pv = sC + v * 432 + b0;
        float acc = 0.f;
#pragma unroll
        for (int i = 0; i < 5; i++)
#pragma unroll
            for (int j = 0; j < 5; j++)
                acc += wm[i * 5 + j] * pv[i * 36 + j];
        ob[(size_t)v * HW] = (acc - C) * sw[64 + v] + sb[64 + v];
    }
}

// ---------------------------------------------------------------------------
extern "C" void kernel_launch(void* const* d_in, const int* in_sizes, int n_in,
                              void* d_out, int out_size) {
    const float* x      = (const float*)d_in[0];
    const float* conv_w = (const float*)d_in[1];
    const float* conv_b = (const float*)d_in[2];
    const float* gn_w   = (const float*)d_in[3];
    const float* gn_b   = (const float*)d_in[4];
    float* out = (float*)d_out;

    (void)in_sizes; (void)n_in; (void)out_size;

    const int smem3 = (CHUNK_F + 96 * 2 + 75 * 2) * (int)sizeof(float);  // 56,664 B
    cudaFuncSetAttribute(k_attn, cudaFuncAttributeMaxDynamicSharedMemorySize, smem3);

    dim3 g1(8, 6, B_);
    k_gemm<<<g1, 256>>>(x, conv_w, conv_b);

    dim3 g2(NG, B_);
    k_stats<<<g2, 256>>>();

    dim3 g3(4, NH_, B_);
    k_attn<<<g3, 256, smem3>>>(gn_w, gn_b, out);
}

// round 8
// speedup vs baseline: 2.2322x; 1.3874x over previous
#include <cuda_runtime.h>
#include <cuda_bf16.h>
#include <cstdint>

// Problem constants
#define B_    8
#define CIN   256
#define COUT  768
#define HW    1024
#define NH_   8
#define KS_   32
#define NG    24      // 3*NH groups
#define NPOS  25      // K*K

// Scratch
__device__ float g_attn[(size_t)B_ * COUT * HW];        // 25 MB conv output
__device__ float g_inv[B_ * NG * NPOS];
__device__ float g_mi [B_ * NG * NPOS];
__device__ __nv_bfloat16 g_xh[(size_t)B_ * HW * CIN];   // x^T hi split [b][hw][c]
__device__ __nv_bfloat16 g_xl[(size_t)B_ * HW * CIN];   // x^T lo split
__device__ __nv_bfloat16 g_wh[COUT * CIN];              // w hi split [o][c]
__device__ __nv_bfloat16 g_wl[COUT * CIN];

// ------------------------- PTX helpers (base sm_103-safe) -------------------
__device__ __forceinline__ uint32_t smem_u32(const void* p) {
    uint32_t a;
    asm("{ .reg .u64 t; cvta.to.shared.u64 t, %1; cvt.u32.u64 %0, t; }"
        : "=r"(a) : "l"(p));
    return a;
}
__device__ __forceinline__ void cp_async16(uint32_t saddr, const void* gaddr) {
    asm volatile("cp.async.cg.shared.global [%0], [%1], 16;"
                 :: "r"(saddr), "l"(gaddr) : "memory");
}
__device__ __forceinline__ void cp_commit() {
    asm volatile("cp.async.commit_group;" ::: "memory");
}
template <int N>
__device__ __forceinline__ void cp_wait() {
    asm volatile("cp.async.wait_group %0;" :: "n"(N) : "memory");
}
__device__ __forceinline__ void ldsm4(uint32_t r[4], uint32_t addr) {
    asm volatile("ldmatrix.sync.aligned.m8n8.x4.shared.b16 {%0,%1,%2,%3}, [%4];"
                 : "=r"(r[0]), "=r"(r[1]), "=r"(r[2]), "=r"(r[3]) : "r"(addr));
}
__device__ __forceinline__ void ldsm2(uint32_t r[2], uint32_t addr) {
    asm volatile("ldmatrix.sync.aligned.m8n8.x2.shared.b16 {%0,%1}, [%2];"
                 : "=r"(r[0]), "=r"(r[1]) : "r"(addr));
}
__device__ __forceinline__ void mma16816(float d[4], const uint32_t a[4],
                                         const uint32_t b[2]) {
    asm volatile(
        "mma.sync.aligned.m16n8k16.row.col.f32.bf16.bf16.f32 "
        "{%0,%1,%2,%3}, {%4,%5,%6,%7}, {%8,%9}, {%0,%1,%2,%3};"
        : "+f"(d[0]), "+f"(d[1]), "+f"(d[2]), "+f"(d[3])
        : "r"(a[0]), "r"(a[1]), "r"(a[2]), "r"(a[3]), "r"(b[0]), "r"(b[1]));
}

// ---------------------------------------------------------------------------
// Kernel 0a: transpose + bf16-split x:  [b][c][hw] fp32 -> [b][hw][c] bf16 x2
// ---------------------------------------------------------------------------
__global__ __launch_bounds__(256) void k_cvt_x(const float* __restrict__ x) {
    __shared__ float t[32][33];
    const int b  = blockIdx.z;
    const int c0 = blockIdx.y * 32;
    const int h0 = blockIdx.x * 32;
    const int w = threadIdx.x >> 5, l = threadIdx.x & 31;
    const float* xp = x + ((size_t)b * CIN + c0) * HW + h0;
#pragma unroll
    for (int i = 0; i < 4; i++)
        t[w * 4 + i][l] = xp[(size_t)(w * 4 + i) * HW + l];
    __syncthreads();
#pragma unroll
    for (int i = 0; i < 4; i++) {
        int hw = h0 + w * 4 + i;
        float v = t[l][w * 4 + i];
        __nv_bfloat16 hi = __float2bfloat16(v);
        __nv_bfloat16 lo = __float2bfloat16(v - __bfloat162float(hi));
        size_t o = ((size_t)b * HW + hw) * CIN + c0 + l;
        g_xh[o] = hi;
        g_xl[o] = lo;
    }
}

// Kernel 0b: bf16-split w (already K-major)
__global__ __launch_bounds__(256) void k_cvt_w(const float* __restrict__ w) {
    int i = blockIdx.x * 256 + threadIdx.x;
    float v = w[i];
    __nv_bfloat16 hi = __float2bfloat16(v);
    g_wh[i] = hi;
    g_wl[i] = __float2bfloat16(v - __bfloat162float(hi));
}

// ---------------------------------------------------------------------------
// Kernel 1: mma.sync bf16x3 GEMM.  D[o, hw] = w @ x^T, fp32 accum in regs.
// CTA: 128(M=o) x 128(N=hw), K=256 chunked at 64, double-buffered cp.async.
// Warp grid 2x4 -> warp tile 64x32. Smem rows padded to 72 bf16 (144B) so
// ldmatrix 8-row groups spread across all banks (144 mod 128 = 16B shift).
// smem: bf16[2 buf][2 split][128 rows][72]  A then B -> 147,456 B dynamic.
// ---------------------------------------------------------------------------
#define SAS    72
#define TILE_E (128 * SAS)          // 9216 bf16 per (buf,split) tile
#define BOFF_E (4 * TILE_E)         // B region starts after A's 4 tiles

extern __shared__ __align__(16) __nv_bfloat16 smg[];

__global__ __launch_bounds__(256, 1)
void k_gemm_mma(const float* __restrict__ bias) {
    const uint32_t sb = smem_u32(smg);
    const int tid  = threadIdx.x;
    const int wid  = tid >> 5;
    const int lane = tid & 31;
    const int n0 = blockIdx.x * 128;   // hw tile
    const int m0 = blockIdx.y * 128;   // o tile
    const int b  = blockIdx.z;

    const __nv_bfloat16* gA[2] = { g_wh + (size_t)m0 * CIN,
                                   g_wl + (size_t)m0 * CIN };
    const __nv_bfloat16* gB[2] = { g_xh + ((size_t)b * HW + n0) * CIN,
                                   g_xl + ((size_t)b * HW + n0) * CIN };

    const int lr = tid >> 3;           // 0..31 (row block helper for loads)
    const int lc = tid & 7;            // 16B chunk within 64-col row

    auto issue = [&](int kc, int buf) {
        const int k0 = kc * 64;
#pragma unroll
        for (int s = 0; s < 2; s++) {
#pragma unroll
            for (int i = 0; i < 4; i++) {           // A: 1024 chunks / 256 thr
                int r = lr + i * 32;
                cp_async16(sb + (uint32_t)(((buf * 2 + s) * TILE_E + r * SAS + lc * 8) * 2),
                           gA[s] + (size_t)r * CIN + k0 + lc * 8);
            }
#pragma unroll
            for (int i = 0; i < 4; i++) {           // B: 1024 chunks
                int r = lr + i * 32;
                cp_async16(sb + (uint32_t)((BOFF_E + (buf * 2 + s) * TILE_E + r * SAS + lc * 8) * 2),
                           gB[s] + (size_t)r * CIN + k0 + lc * 8);
            }
        }
        cp_commit();
    };

    float d[4][4][4];
#pragma unroll
    for (int mi = 0; mi < 4; mi++)
#pragma unroll
        for (int ni = 0; ni < 4; ni++)
#pragma unroll
            for (int j = 0; j < 4; j++) d[mi][ni][j] = 0.f;

    const int m_base = (wid >> 2) * 64;
    const int n_base = (wid & 3) * 32;
    // ldmatrix lane address components
    const int a_row = (lane & 7) + ((lane >> 3) & 1) * 8;  // within 16-row frag
    const int a_kof = (lane >> 4) * 8;                      // k offset 0/8
    const int b_row = lane & 7;                             // within 8-row frag
    const int b_kof = ((lane >> 3) & 1) * 8;

    issue(0, 0);

    for (int kc = 0; kc < 4; kc++) {
        if (kc < 3) issue(kc + 1, (kc + 1) & 1);
        if (kc < 3) cp_wait<1>(); else cp_wait<0>();
        __syncthreads();

        const int buf = kc & 1;
        const uint32_t aB0 = sb + (uint32_t)(((buf * 2 + 0) * TILE_E) * 2);
        const uint32_t aB1 = sb + (uint32_t)(((buf * 2 + 1) * TILE_E) * 2);
        const uint32_t bB0 = sb + (uint32_t)((BOFF_E + (buf * 2 + 0) * TILE_E) * 2);
        const uint32_t bB1 = sb + (uint32_t)((BOFF_E + (buf * 2 + 1) * TILE_E) * 2);

#pragma unroll
        for (int ks = 0; ks < 4; ks++) {
            const int k0 = ks * 16;
            uint32_t ah[4][4], al[4][4], bh[4][2], bl[4][2];
#pragma unroll
            for (int mi = 0; mi < 4; mi++) {
                const uint32_t off =
                    (uint32_t)(((m_base + mi * 16 + a_row) * SAS + k0 + a_kof) * 2);
                ldsm4(ah[mi], aB0 + off);
                ldsm4(al[mi], aB1 + off);
            }
#pragma unroll
            for (int ni = 0; ni < 4; ni++) {
                const uint32_t off =
                    (uint32_t)(((n_base + ni * 8 + b_row) * SAS + k0 + b_kof) * 2);
                ldsm2(bh[ni], bB0 + off);
                ldsm2(bl[ni], bB1 + off);
            }
#pragma unroll
            for (int mi = 0; mi < 4; mi++)
#pragma unroll
                for (int ni = 0; ni < 4; ni++) {
                    mma16816(d[mi][ni], ah[mi], bh[ni]);
                    mma16816(d[mi][ni], ah[mi], bl[ni]);
                    mma16816(d[mi][ni], al[mi], bh[ni]);
                }
        }
        __syncthreads();
    }

    // ---- epilogue: direct float2 stores, D rows = o, cols = hw ----
    const int qr = lane >> 2;          // 0..7
    const int qc = (lane & 3) * 2;     // 0,2,4,6
#pragma unroll
    for (int mi = 0; mi < 4; mi++) {
        const int r0 = m0 + m_base + mi * 16 + qr;
        const float bz0 = __ldg(bias + r0);
        const float bz1 = __ldg(bias + r0 + 8);
        float* p0 = g_attn + ((size_t)b * COUT + r0) * HW + n0 + n_base + qc;
        float* p1 = p0 + (size_t)8 * HW;
#pragma unroll
        for (int ni = 0; ni < 4; ni++) {
            *reinterpret_cast<float2*>(p0 + ni * 8) =
                make_float2(d[mi][ni][0] + bz0, d[mi][ni][1] + bz0);
            *reinterpret_cast<float2*>(p1 + ni * 8) =
                make_float2(d[mi][ni][2] + bz1, d[mi][ni][3] + bz1);
        }
    }
}

// ---------------------------------------------------------------------------
// Kernel 2: GN stats via separable edge algebra (unchanged).
// ---------------------------------------------------------------------------
__global__ __launch_bounds__(256) void k_stats() {
    const int g = blockIdx.x;
    const int b = blockIdx.y;
    const float* base = g_attn + ((size_t)b * COUT + g * KS_) * HW;

    __shared__ float rowdat[32][10];
    __shared__ float edge[4][10];

    for (int i = threadIdx.x; i < 320; i += 256) ((float*)rowdat)[i] = 0.f;
    __syncthreads();

    const int r   = threadIdx.x & 31;
    const int ch0 = threadIdx.x >> 5;

    float sf = 0, qf = 0, s0 = 0, q0 = 0, s1 = 0, q1 = 0,
          s30 = 0, q30 = 0, s31 = 0, q31 = 0;
#pragma unroll
    for (int it = 0; it < 4; it++) {
        const int ch = ch0 + it * 8;
        const float4* row = (const float4*)(base + (size_t)ch * HW + r * 32);
#pragma unroll
        for (int jj = 0; jj < 8; jj++) {
            float4 v = row[jj];
            sf += v.x + v.y + v.z + v.w;
            qf += v.x * v.x + v.y * v.y + v.z * v.z + v.w * v.w;
            if (jj == 0) { s0 += v.x; q0 += v.x * v.x; s1 += v.y; q1 += v.y * v.y; }
            if (jj == 7) { s30 += v.z; q30 += v.z * v.z; s31 += v.w; q31 += v.w * v.w; }
        }
    }
    atomicAdd(&rowdat[r][0], sf);  atomicAdd(&rowdat[r][1], qf);
    atomicAdd(&rowdat[r][2], s0);  atomicAdd(&rowdat[r][3], q0);
    atomicAdd(&rowdat[r][4], s1);  atomicAdd(&rowdat[r][5], q1);
    atomicAdd(&rowdat[r][6], s30); atomicAdd(&rowdat[r][7], q30);
    atomicAdd(&rowdat[r][8], s31); atomicAdd(&rowdat[r][9], q31);
    __syncthreads();

    if (threadIdx.x < 32) {
        const int l = threadIdx.x;
        float F  = rowdat[l][0], QF = rowdat[l][1];
        float E0 = rowdat[l][2], Q0 = rowdat[l][3];
        float E1 = rowdat[l][4], Q1 = rowdat[l][5];
        float E30 = rowdat[l][6], Q30 = rowdat[l][7];
        float E31 = rowdat[l][8], Q31 = rowdat[l][9];

        float rs[5], rq[5];
        rs[0] = F - E30 - E31; rq[0] = QF - Q30 - Q31;
        rs[1] = F - E31;       rq[1] = QF - Q31;
        rs[2] = F;             rq[2] = QF;
        rs[3] = F - E0;        rq[3] = QF - Q0;
        rs[4] = F - E0 - E1;   rq[4] = QF - Q0 - Q1;

        float ts[5], tq[5];
#pragma unroll
        for (int j = 0; j < 5; j++) { ts[j] = rs[j]; tq[j] = rq[j]; }
#pragma unroll
        for (int o = 16; o > 0; o >>= 1)
#pragma unroll
            for (int j = 0; j < 5; j++) {
                ts[j] += __shfl_xor_sync(0xFFFFFFFFu, ts[j], o);
                tq[j] += __shfl_xor_sync(0xFFFFFFFFu, tq[j], o);
            }

        int ei = (l == 0) ? 0 : (l == 1) ? 1 : (l == 30) ? 2 : (l == 31) ? 3 : -1;
        if (ei >= 0)
#pragma unroll
            for (int j = 0; j < 5; j++) { edge[ei][j] = rs[j]; edge[ei][5 + j] = rq[j]; }
        __syncwarp();

        if (l < 25) {
            const int i = l / 5, j = l % 5;
            float S = ts[j], Q = tq[j];
            if (i == 0)      { S -= edge[2][j] + edge[3][j]; Q -= edge[2][5+j] + edge[3][5+j]; }
            else if (i == 1) { S -= edge[3][j];              Q -= edge[3][5+j]; }
            else if (i == 3) { S -= edge[0][j];              Q -= edge[0][5+j]; }
            else if (i == 4) { S -= edge[0][j] + edge[1][j]; Q -= edge[0][5+j] + edge[1][5+j]; }
            const float invN = 1.f / 32768.f;
            float mean = S * invN;
            float var  = Q * invN - mean * mean;
            float inv  = rsqrtf(var + 1e-5f);
            int o = (b * NG + g) * NPOS + l;
            g_inv[o] = inv;
            g_mi[o]  = mean * inv;
        }
    }
}

// ---------------------------------------------------------------------------
// Kernel 3: local attention (unchanged).
// ---------------------------------------------------------------------------
#define CHUNK_F (32 * 12 * 36)

extern __shared__ float sm3[];

__global__ __launch_bounds__(256, 2) void k_attn(const float* __restrict__ gnw,
                                                 const float* __restrict__ gnb,
                                                 float* __restrict__ out) {
    const int b   = blockIdx.z;
    const int nh  = blockIdx.y;
    const int oh0 = blockIdx.x * 8;
    const int tid  = threadIdx.x;
    const int warp = tid >> 5;
    const int lane = tid & 31;

    float* sC   = sm3;
    float* sw   = sC + CHUNK_F;
    float* sb   = sw + 96;
    float* sinv = sb + 96;
    float* smi  = sinv + 75;

    if (tid < 96) { sw[tid] = gnw[nh * 96 + tid]; sb[tid] = gnb[nh * 96 + tid]; }
    if (tid < 75) {
        int gg = tid / 25, p = tid - gg * 25;
        int src = (b * NG + nh * 3 + gg) * NPOS + p;
        sinv[tid] = g_inv[src];
        smi[tid]  = g_mi[src];
    }

    const float* abase = g_attn + ((size_t)b * COUT + nh * 96) * HW;

    auto stage = [&](int cb) {
        for (int idx = tid; idx < CHUNK_F; idx += 256) {
            int ch  = idx / 432;
            int rem = idx - ch * 432;
            int lr  = rem / 36;
            int lc  = rem - lr * 36;
            int gh = oh0 - 2 + lr;
            int gw = lc - 2;
            float v = 0.f;
            if ((unsigned)gh < 32u && (unsigned)gw < 32u)
                v = abase[(size_t)(cb + ch) * HW + gh * 32 + gw];
            sC[idx] = v;
        }
    };

    const int b0 = warp * 36 + lane;

    stage(32);
    __syncthreads();

    float invq[25];
    float misum = 0.f;
#pragma unroll
    for (int p = 0; p < 25; p++) { invq[p] = sinv[25 + p]; misum += smi[25 + p]; }

    float q[32];
#pragma unroll
    for (int v = 0; v < 32; v++) {
        const float* pv = sC + v * 432 + b0;
        float acc = 0.f;
#pragma unroll
        for (int i = 0; i < 5; i++)
#pragma unroll
            for (int j = 0; j < 5; j++)
                acc += pv[i * 36 + j] * invq[i * 5 + j];
        q[v] = (acc - misum) * 0.04f * sw[32 + v] + sb[32 + v];
    }

    __syncthreads();
    stage(0);
    __syncthreads();

    float G1 = 0.f, Sqb = 0.f;
#pragma unroll
    for (int v = 0; v < 32; v++) {
        float qg = q[v] * sw[v];
        Sqb += q[v] * sb[v];
        q[v] = qg;
        G1 += qg;
    }

    float sal[25];
#pragma unroll
    for (int i = 0; i < 5; i++)
#pragma unroll
        for (int j = 0; j < 5; j++) {
            const float* pk = sC + b0 + i * 36 + j;
            float dot = 0.f;
#pragma unroll
            for (int v = 0; v < 32; v++)
                dot += q[v] * pk[v * 432];
            const int p = i * 5 + j;
            sal[p] = (sinv[p] * dot - smi[p] * G1 + Sqb) * 0.17677669529663687f;
        }

    float mmax = sal[0];
#pragma unroll
    for (int p = 1; p < 25; p++) mmax = fmaxf(mmax, sal[p]);
    float ssum = 0.f;
#pragma unroll
    for (int p = 0; p < 25; p++) { sal[p] = __expf(sal[p] - mmax); ssum += sal[p]; }
    const float rsum = 1.f / ssum;

    float wm[25];
    float C = 0.f;
#pragma unroll
    for (int p = 0; p < 25; p++) {
        float mk = sal[p] * rsum;
        wm[p] = mk * sinv[50 + p];
        C += mk * smi[50 + p];
    }

    __syncthreads();
    stage(64);
    __syncthreads();

    float* ob = out + ((size_t)(b * 256 + nh * 32)) * HW + (oh0 + warp) * 32 + lane;
#pragma unroll 4
    for (int v = 0; v < 32; v++) {
        const float* pv = sC + v * 432 + b0;
        float acc = 0.f;
#pragma unroll
        for (int i = 0; i < 5; i++)
#pragma unroll
            for (int j = 0; j < 5; j++)
                acc += wm[i * 5 + j] * pv[i * 36 + j];
        ob[(size_t)v * HW] = (acc - C) * sw[64 + v] + sb[64 + v];
    }
}

// ---------------------------------------------------------------------------
extern "C" void kernel_launch(void* const* d_in, const int* in_sizes, int n_in,
                              void* d_out, int out_size) {
    const float* x      = (const float*)d_in[0];
    const float* conv_w = (const float*)d_in[1];
    const float* conv_b = (const float*)d_in[2];
    const float* gn_w   = (const float*)d_in[3];
    const float* gn_b   = (const float*)d_in[4];
    float* out = (float*)d_out;

    (void)in_sizes; (void)n_in; (void)out_size;

    const int smemG = 8 * TILE_E * 2;   // 147,456 B
    cudaFuncSetAttribute(k_gemm_mma, cudaFuncAttributeMaxDynamicSharedMemorySize, smemG);
    const int smem3 = (CHUNK_F + 96 * 2 + 75 * 2) * (int)sizeof(float);
    cudaFuncSetAttribute(k_attn, cudaFuncAttributeMaxDynamicSharedMemorySize, smem3);

    dim3 gc(32, 8, B_);                 // hw-tiles, c-tiles, batch
    k_cvt_x<<<gc, 256>>>(x);
    k_cvt_w<<<768, 256>>>(conv_w);

    dim3 g1(8, 6, B_);                  // hw-tiles(128), o-tiles(128), batch
    k_gemm_mma<<<g1, 256, smemG>>>(conv_b);

    dim3 g2(NG, B_);
    k_stats<<<g2, 256>>>();

    dim3 g3(4, NH_, B_);
    k_attn<<<g3, 256, smem3>>>(gn_w, gn_b, out);
}